// round 16
// baseline (speedup 1.0000x reference)
#include <cuda_runtime.h>
#include <cuda_bf16.h>
#include <cstdint>
#include <cstddef>

// ---------------------------------------------------------------------------
// Problem constants
// ---------------------------------------------------------------------------
#define BATCH   256
#define SEQ     512
#define NIN     256
#define HID     256
#define G3      768
#define LAYERS  2
#define ROWS    (BATCH*SEQ)
#define RANKSUM 96

// ---------------------------------------------------------------------------
// Static device scratch (no cudaMalloc allowed)
// ---------------------------------------------------------------------------
__device__ float g_wx_buf[(size_t)ROWS * G3];
__device__ float g_x1[(size_t)ROWS * HID];
__device__ float g_Pu[LAYERS * HID * RANKSUM];
__device__ float g_Qu[LAYERS * RANKSUM * G3];

// Q as bf16 hi/lo: [layer][n 768][hi 96 | lo 96]
__device__ __nv_bfloat16 g_q16[(size_t)LAYERS * G3 * 192];
// P^T as bf16 hi/lo: [layer][n 96][hi 256 | lo 256]
__device__ __nv_bfloat16 g_p16[(size_t)LAYERS * 96 * 512];

// U as bf16 hi/lo in B-operand layout: per (layer, cta): [96 n][264 k-padded]
#define BPAD  264                         // 528 bytes per row (bank step 4)
#define BTILE (96 * BPAD)                 // elems per (l, c) per precision
__device__ __nv_bfloat16 g_Uhi[(size_t)LAYERS * 8 * BTILE];
__device__ __nv_bfloat16 g_Ulo[(size_t)LAYERS * 8 * BTILE];

// h exchange (L2-resident): A-tile images [buf 2][group 16][hi 12288B | lo 12288B]
__device__ __nv_bfloat16 g_hx[2 * 16 * 2 * 6144];

// ---------------------------------------------------------------------------
// PTX helpers (baseline-target-safe: ldmatrix + mma.sync only)
// ---------------------------------------------------------------------------
__device__ __forceinline__ uint32_t smem_u32(const void* p)
{
    uint32_t a;
    asm("{ .reg .u64 t; cvta.to.shared.u64 t, %1; cvt.u32.u64 %0, t; }"
        : "=r"(a) : "l"(p));
    return a;
}

#define LDSM4(R, addr) \
    asm volatile("ldmatrix.sync.aligned.m8n8.x4.shared.b16 {%0,%1,%2,%3}, [%4];" \
        : "=r"((R)[0]), "=r"((R)[1]), "=r"((R)[2]), "=r"((R)[3]) : "r"(addr))
#define MMA16816(D, A, B) \
    asm volatile("mma.sync.aligned.m16n8k16.row.col.f32.bf16.bf16.f32 " \
        "{%0,%1,%2,%3}, {%4,%5,%6,%7}, {%8,%9}, {%0,%1,%2,%3};" \
        : "+f"((D)[0]), "+f"((D)[1]), "+f"((D)[2]), "+f"((D)[3]) \
        : "r"((A)[0]), "r"((A)[1]), "r"((A)[2]), "r"((A)[3]), \
          "r"((B)[0]), "r"((B)[1]))

__device__ __forceinline__ uint32_t pack_hi2(float a, float b, uint32_t& lo)
{
    __nv_bfloat16 h0 = __float2bfloat16(a);
    __nv_bfloat16 h1 = __float2bfloat16(b);
    __nv_bfloat16 l0 = __float2bfloat16(a - __bfloat162float(h0));
    __nv_bfloat16 l1 = __float2bfloat16(b - __bfloat162float(h1));
    lo = (uint32_t)__bfloat16_as_ushort(l0) |
         ((uint32_t)__bfloat16_as_ushort(l1) << 16);
    return (uint32_t)__bfloat16_as_ushort(h0) |
           ((uint32_t)__bfloat16_as_ushort(h1) << 16);
}

// ---------------------------------------------------------------------------
// Pack kernel: Pu/Qu (fp32, for ueff) + q16/p16 hi/lo (direct from inputs)
// ---------------------------------------------------------------------------
__global__ void pack_kernel(const float* __restrict__ Wd, const float* __restrict__ Wdg,
                            const float* __restrict__ Wo, const float* __restrict__ Wog,
                            const float* __restrict__ Ud, const float* __restrict__ Udg,
                            const float* __restrict__ Uo, const float* __restrict__ Uog)
{
    int idx = blockIdx.x * 256 + threadIdx.x;
    const int QN = LAYERS * RANKSUM * G3;
    const int PN = LAYERS * NIN * RANKSUM;
    const int P16N = LAYERS * 96 * 256;
    if (idx < QN) {
        int l = idx / (RANKSUM * G3);
        int rem = idx - l * (RANKSUM * G3);
        int r = rem / G3, n = rem - r * G3;
        g_Qu[idx] = (r < 64) ? Udg[(l*64 + r) * G3 + n] : Uog[(l*32 + (r-64)) * G3 + n];
        int k = idx % 96;
        int n2 = (idx / 96) % G3;
        int l2 = idx / (96 * G3);
        float v = (k < 64) ? Wdg[(l2*64 + k) * G3 + n2]
                           : Wog[(l2*32 + (k-64)) * G3 + n2];
        __nv_bfloat16 hi = __float2bfloat16(v);
        __nv_bfloat16 lo = __float2bfloat16(v - __bfloat162float(hi));
        size_t o = ((size_t)l2 * G3 + n2) * 192 + k;
        g_q16[o]      = hi;
        g_q16[o + 96] = lo;
    }
    if (idx < PN) {
        int l = idx / (NIN * RANKSUM);
        int rem = idx - l * (NIN * RANKSUM);
        int k = rem / RANKSUM, j = rem - k * RANKSUM;
        g_Pu[idx] = (j < 64) ? Ud[(l*NIN + k) * 64 + j] : Uo[(l*NIN + k) * 32 + (j-64)];
    }
    if (idx < P16N) {
        int k = idx & 255;
        int n = (idx >> 8) % 96;
        int l = idx / (96 * 256);
        float v = (n < 64) ? Wd[(l*NIN + k) * 64 + n]
                           : Wo[(l*NIN + k) * 32 + (n-64)];
        __nv_bfloat16 hi = __float2bfloat16(v);
        __nv_bfloat16 lo = __float2bfloat16(v - __bfloat162float(hi));
        size_t o = ((size_t)l * 96 + n) * 512 + k;
        g_p16[o]       = hi;
        g_p16[o + 256] = lo;
    }
}

// ---------------------------------------------------------------------------
// Ueff GEMM with fused hi/lo B-layout split epilogue.
// ---------------------------------------------------------------------------
__global__ void __launch_bounds__(256)
gemm_ueff(const float* __restrict__ Pu, const float* __restrict__ Qu)
{
    __shared__ float As[16][64];
    __shared__ float Bs[16][68];

    const int l = blockIdx.z;
    const float* A = Pu + (size_t)l * HID * RANKSUM;
    const float* B = Qu + (size_t)l * RANKSUM * G3;

    const int tid = threadIdx.x;
    const int tm = tid >> 4, tn = tid & 15;
    const int bm = blockIdx.x * 64;
    const int bn = blockIdx.y * 64;

    const int ar = tid >> 2, ak = (tid & 3) << 2;
    const int brow = tid >> 4, bcol = (tid & 15) << 2;

    float acc[4][4];
#pragma unroll
    for (int i = 0; i < 4; ++i)
#pragma unroll
        for (int j = 0; j < 4; ++j) acc[i][j] = 0.f;

    for (int k0 = 0; k0 < RANKSUM; k0 += 16) {
        float4 av = *(const float4*)(A + (bm + ar) * RANKSUM + k0 + ak);
        As[ak + 0][ar] = av.x; As[ak + 1][ar] = av.y;
        As[ak + 2][ar] = av.z; As[ak + 3][ar] = av.w;

        float4 bv = *(const float4*)(B + (size_t)(k0 + brow) * G3 + bn + bcol);
        *(float4*)&Bs[brow][bcol] = bv;
        __syncthreads();

#pragma unroll
        for (int k = 0; k < 16; ++k) {
            float4 a = *(const float4*)&As[k][tm << 2];
            float4 b = *(const float4*)&Bs[k][tn << 2];
            acc[0][0] = fmaf(a.x, b.x, acc[0][0]); acc[0][1] = fmaf(a.x, b.y, acc[0][1]);
            acc[0][2] = fmaf(a.x, b.z, acc[0][2]); acc[0][3] = fmaf(a.x, b.w, acc[0][3]);
            acc[1][0] = fmaf(a.y, b.x, acc[1][0]); acc[1][1] = fmaf(a.y, b.y, acc[1][1]);
            acc[1][2] = fmaf(a.y, b.z, acc[1][2]); acc[1][3] = fmaf(a.y, b.w, acc[1][3]);
            acc[2][0] = fmaf(a.z, b.x, acc[2][0]); acc[2][1] = fmaf(a.z, b.y, acc[2][1]);
            acc[2][2] = fmaf(a.z, b.z, acc[2][2]); acc[2][3] = fmaf(a.z, b.w, acc[2][3]);
            acc[3][0] = fmaf(a.w, b.x, acc[3][0]); acc[3][1] = fmaf(a.w, b.y, acc[3][1]);
            acc[3][2] = fmaf(a.w, b.z, acc[3][2]); acc[3][3] = fmaf(a.w, b.w, acc[3][3]);
        }
        __syncthreads();
    }

#pragma unroll
    for (int i = 0; i < 4; ++i) {
        int k = bm + (tm << 2) + i;
#pragma unroll
        for (int j = 0; j < 4; ++j) {
            int col = bn + (tn << 2) + j;
            int c = (col >> 5) & 7;
            int n = ((col >> 8) << 5) + (col & 31);
            float v = acc[i][j];
            __nv_bfloat16 hi = __float2bfloat16(v);
            __nv_bfloat16 lo = __float2bfloat16(v - __bfloat162float(hi));
            size_t o = ((size_t)l * 8 + c) * BTILE + n * BPAD + k;
            g_Uhi[o] = hi;
            g_Ulo[o] = lo;
        }
    }
}

// ---------------------------------------------------------------------------
// Fused stage-1 + stage-2 GEMM (unchanged R15 winner)
// ---------------------------------------------------------------------------
#define FX_T_BYTES (128 * 416)
#define FX_B_BYTES (64 * 416)
#define FX_SMEM    (FX_T_BYTES + FX_B_BYTES)

__global__ void __launch_bounds__(256)
s1wx_hmma(const float* __restrict__ x,
          const __nv_bfloat16* __restrict__ P16,
          const __nv_bfloat16* __restrict__ Q16,
          const float* __restrict__ bias,
          float* __restrict__ C)
{
    extern __shared__ char sm[];
    char* sT = sm;
    char* sB = sm + FX_T_BYTES;

    const int tid = threadIdx.x;
    const int w = tid >> 5, lane = tid & 31;
    const int wm = w >> 1, wn = w & 1;
    const size_t bm = (size_t)blockIdx.x * 128;

    const uint32_t sTu = smem_u32(sT);
    const uint32_t sBu = smem_u32(sB);

    const int rr = lane & 7;
    const int q = lane >> 3;
    const int er = lane >> 2;
    const int ec = (lane & 3) << 1;

    // ================= phase 1: T = x @ P16^T =================
    {
        const uint32_t a1off = (uint32_t)((wm * 32 + ((lane >> 3) & 1) * 8 + rr) * 272
                                          + (lane >> 4) * 16);
        const uint32_t b1off = (uint32_t)(rr * 272 + ((q >> 1) * 128) + (q & 1) * 16);

        float acc1[2][6][4];
#pragma unroll
        for (int mt = 0; mt < 2; ++mt)
#pragma unroll
            for (int nt = 0; nt < 6; ++nt)
#pragma unroll
                for (int i = 0; i < 4; ++i) acc1[mt][nt][i] = 0.f;

        const int crow = tid >> 1, chalf = tid & 1;

        for (int kc = 0; kc < 4; ++kc) {
            {
                const float4* src = (const float4*)(x + (bm + crow) * NIN
                                                    + kc * 64 + chalf * 32);
                char* dst = sT + crow * 272 + chalf * 64;
#pragma unroll
                for (int i = 0; i < 8; ++i) {
                    float4 v = src[i];
                    uint32_t lw0, lw1;
                    uint32_t hw0 = pack_hi2(v.x, v.y, lw0);
                    uint32_t hw1 = pack_hi2(v.z, v.w, lw1);
                    *(uint32_t*)(dst + i * 8)           = hw0;
                    *(uint32_t*)(dst + i * 8 + 4)       = hw1;
                    *(uint32_t*)(dst + 128 + i * 8)     = lw0;
                    *(uint32_t*)(dst + 128 + i * 8 + 4) = lw1;
                }
            }
            {
#pragma unroll
                for (int it = 0; it < 6; ++it) {
                    int u = tid + 256 * it;
                    int n = u >> 4;
                    int part = (u >> 3) & 1;
                    int i = u & 7;
                    const uint4* src = (const uint4*)(P16 + (size_t)n * 512
                                                      + part * 256 + kc * 64) + i;
                    *(uint4*)(sB + n * 272 + part * 128 + i * 16) = *src;
                }
            }
            __syncthreads();

#pragma unroll
            for (int kt = 0; kt < 4; ++kt) {
                uint32_t ahi[2][4], alo[2][4];
#pragma unroll
                for (int mt = 0; mt < 2; ++mt) {
                    const uint32_t ab = sTu + a1off
                                      + (uint32_t)(mt * 16 * 272 + kt * 32);
                    LDSM4(ahi[mt], ab);
                    LDSM4(alo[mt], ab + 128);
                }
#pragma unroll
                for (int nt = 0; nt < 6; ++nt) {
                    uint32_t bf[4];
                    LDSM4(bf, sBu + b1off
                              + (uint32_t)((wn * 48 + nt * 8) * 272 + kt * 32));
#pragma unroll
                    for (int mt = 0; mt < 2; ++mt) {
                        MMA16816(acc1[mt][nt], ahi[mt], bf);
                        MMA16816(acc1[mt][nt], alo[mt], bf);
                        MMA16816(acc1[mt][nt], ahi[mt], bf + 2);
                    }
                }
            }
            __syncthreads();
        }

#pragma unroll
        for (int nt = 0; nt < 6; ++nt) {
            const int col = wn * 48 + nt * 8 + ec;
#pragma unroll
            for (int mt = 0; mt < 2; ++mt) {
#pragma unroll
                for (int rh = 0; rh < 2; ++rh) {
                    const int rowl = wm * 32 + mt * 16 + er + rh * 8;
                    uint32_t lw;
                    uint32_t hw = pack_hi2(acc1[mt][nt][rh * 2],
                                           acc1[mt][nt][rh * 2 + 1], lw);
                    *(uint32_t*)(sT + rowl * 416 + col * 2)       = hw;
                    *(uint32_t*)(sT + rowl * 416 + 208 + col * 2) = lw;
                }
            }
        }
        __syncthreads();
    }

    // ================= phase 2: wx = T @ Q16^T + bias =================
    {
        const uint32_t a2off = (uint32_t)((wm * 32 + ((lane >> 3) & 1) * 8 + rr) * 416
                                          + (lane >> 4) * 16);
        const uint32_t b2off = (uint32_t)((wn * 32 + rr) * 416 + (q & 1) * 16
                                          + (q >> 1) * 208);

        for (int bnc = 0; bnc < 12; ++bnc) {
            {
                const uint4* srcB = (const uint4*)Q16 + (size_t)(bnc * 64) * 24;
#pragma unroll
                for (int i = 0; i < 6; ++i) {
                    int u = tid + 256 * i;
                    int row = u / 24, ir = u - row * 24;
                    uint32_t off = (uint32_t)(row * 416 + ir * 16
                                              + ((ir >= 12) ? 16 : 0));
                    *(uint4*)(sB + off) = srcB[u];
                }
            }
            __syncthreads();

            float acc2[2][4][4];
#pragma unroll
            for (int mt = 0; mt < 2; ++mt)
#pragma unroll
                for (int nt = 0; nt < 4; ++nt)
#pragma unroll
                    for (int i = 0; i < 4; ++i) acc2[mt][nt][i] = 0.f;

#pragma unroll
            for (int kt = 0; kt < 6; ++kt) {
                uint32_t ahi[2][4], alo[2][4];
#pragma unroll
                for (int mt = 0; mt < 2; ++mt) {
                    const uint32_t ab = sTu + a2off
                                      + (uint32_t)(mt * 16 * 416 + kt * 32);
                    LDSM4(ahi[mt], ab);
                    LDSM4(alo[mt], ab + 208);
                }
#pragma unroll
                for (int nt = 0; nt < 4; ++nt) {
                    uint32_t bf[4];
                    LDSM4(bf, sBu + b2off + (uint32_t)(nt * 8 * 416 + kt * 32));
#pragma unroll
                    for (int mt = 0; mt < 2; ++mt) {
                        MMA16816(acc2[mt][nt], ahi[mt], bf);
                        MMA16816(acc2[mt][nt], alo[mt], bf);
                        MMA16816(acc2[mt][nt], ahi[mt], bf + 2);
                    }
                }
            }

#pragma unroll
            for (int nt = 0; nt < 4; ++nt) {
                const int col = bnc * 64 + wn * 32 + nt * 8 + ec;
                const float b0 = bias[col], b1 = bias[col + 1];
#pragma unroll
                for (int mt = 0; mt < 2; ++mt) {
                    const size_t r0 = bm + wm * 32 + mt * 16 + er;
                    *(float2*)(C + r0 * G3 + col) =
                        make_float2(acc2[mt][nt][0] + b0, acc2[mt][nt][1] + b1);
                    *(float2*)(C + (r0 + 8) * G3 + col) =
                        make_float2(acc2[mt][nt][2] + b0, acc2[mt][nt][3] + b1);
                }
            }
            __syncthreads();
        }
    }
}

__device__ __forceinline__ float sigmoidf_(float x)
{
    return __fdividef(1.f, 1.f + __expf(-x));
}
__device__ __forceinline__ float tanhf_(float x)
{
    return __fdividef(2.f, 1.f + __expf(-2.f * x)) - 1.f;
}

// ---------------------------------------------------------------------------
// HMMA recurrent kernel v7: two batch groups per cluster, interleaved so each
// cluster barrier's flight/skew is hidden under the other group's MMA work.
// Grid 64 CTAs = 8 clusters x 8; each cluster owns groups {2cl, 2cl+1}.
// Inner math identical to R11/R15 winner. 2 barriers/t, separate redA/redB.
// ---------------------------------------------------------------------------
#define A_BYTES  24576
#define B_BYTES  (BTILE * 2)
#define RED_BYTES (3 * 4 * 32 * 12 * 4)   // 18432
#define RNN_SMEM (2 * A_BYTES + 2 * B_BYTES + 2 * RED_BYTES)   // 187392

__global__ void __cluster_dims__(8, 1, 1) __launch_bounds__(512, 1)
rnn_hmma(const __nv_bfloat16* __restrict__ Uhi8,
         const __nv_bfloat16* __restrict__ Ulo8,
         const float* __restrict__ wx,
         float* __restrict__ out_x,
         float* __restrict__ hT_out,
         __nv_bfloat16* __restrict__ hx)
{
    extern __shared__ char sm[];
    char* sA0 = sm;                         // group A image [hi|lo]
    char* sA1 = sm + A_BYTES;               // group B image
    char* sBh = sm + 2 * A_BYTES;
    char* sBl = sBh + B_BYTES;
    float* redA = (float*)(sBl + B_BYTES);
    float* redB = redA + RED_BYTES / 4;

    const int c  = blockIdx.x & 7;
    const int cl = blockIdx.x >> 3;          // cluster id 0..7
    const int gA = cl * 2, gB = cl * 2 + 1;  // owned batch groups
    const int tid = threadIdx.x;
    const int w = tid >> 5, lane = tid & 31;
    const int kq = w >> 2;
    const int cg = w & 3;

    {
        const uint4* s0 = (const uint4*)(Uhi8 + (size_t)c * BTILE);
        const uint4* s1 = (const uint4*)(Ulo8 + (size_t)c * BTILE);
        uint4* d0 = (uint4*)sBh;
        uint4* d1 = (uint4*)sBl;
        for (int i = tid; i < B_BYTES / 16; i += 512) { d0[i] = s0[i]; d1[i] = s1[i]; }
        uint4 z4 = make_uint4(0u, 0u, 0u, 0u);
        uint4* a0 = (uint4*)sA0;
        uint4* a1 = (uint4*)sA1;
        for (int i = tid; i < A_BYTES / 16; i += 512) { a0[i] = z4; a1[i] = z4; }
    }
    __syncthreads();

    const uint32_t sA0u = smem_u32(sA0);
    const uint32_t sA1u = smem_u32(sA1);
    const uint32_t sBhu = smem_u32(sBh);
    const uint32_t sBlu = smem_u32(sBl);
    const int q = lane >> 3, rr = lane & 7;
    const uint32_t aoff = (uint32_t)(((q & 1) * 8 + rr) * 48 + (q >> 1) * 16);
    const uint32_t bbase = ((q < 2) ? sBhu : sBlu)
                         + (uint32_t)(rr * 528 + (q & 1) * 16)
                         + (uint32_t)((cg << 3) * 528);
    const uint32_t bz = 0, br = 32 * 528, bc = 64 * 528;

    // hoist B fragments (time-invariant) into registers
    uint32_t bZ[4][4], bR[4][4], bC[4][4];
#pragma unroll
    for (int i = 0; i < 4; ++i) {
        const uint32_t ko = bbase + (uint32_t)(((kq << 2) + i) * 32);
        LDSM4(bZ[i], ko + bz);
        LDSM4(bR[i], ko + br);
        LDSM4(bC[i], ko + bc);
    }

    const int r1 = lane >> 2;
    const int coll = (cg << 3) + ((lane & 3) << 1);
    const int hidg = (c << 5) + coll;
    const int kt = hidg >> 4, kin = hidg & 15;
    const uint32_t po1 = (uint32_t)(kt * 768 + r1 * 48 + kin * 2);
    const uint32_t po2 = po1 + 8 * 48;

    const size_t browA1 = (size_t)(gA * 16 + r1), browA2 = browA1 + 8;
    const size_t browB1 = (size_t)(gB * 16 + r1), browB2 = browB1 + 8;

    float hpA[4] = {0.f, 0.f, 0.f, 0.f};
    float hpB[4] = {0.f, 0.f, 0.f, 0.f};

    for (int t = 0; t < SEQ; ++t) {
        const int nb = (t + 1) & 1;

        // =================== A half ===================
        float2 wxv[3][2];
        if (kq == 0) {
            const float* p1 = wx + (browA1 * SEQ + t) * G3 + hidg;
            const float* p2 = wx + (browA2 * SEQ + t) * G3 + hidg;
            wxv[0][0] = *(const float2*)(p1);       wxv[0][1] = *(const float2*)(p2);
            wxv[1][0] = *(const float2*)(p1 + 256); wxv[1][1] = *(const float2*)(p2 + 256);
            wxv[2][0] = *(const float2*)(p1 + 512); wxv[2][1] = *(const float2*)(p2 + 512);
        }

        float dz[4] = {0.f, 0.f, 0.f, 0.f};
        float dr[4] = {0.f, 0.f, 0.f, 0.f};
        float dc[4] = {0.f, 0.f, 0.f, 0.f};
#pragma unroll
        for (int i = 0; i < 4; ++i) {
            const int ktl = (kq << 2) + i;
            uint32_t ah[4], al[4];
            const uint32_t ab = sA0u + (uint32_t)(ktl * 768) + aoff;
            LDSM4(ah, ab);
            LDSM4(al, ab + 12288);
            MMA16816(dz, ah, bZ[i]); MMA16816(dz, al, bZ[i]); MMA16816(dz, ah, bZ[i] + 2);
            MMA16816(dr, ah, bR[i]); MMA16816(dr, al, bR[i]); MMA16816(dr, ah, bR[i] + 2);
            MMA16816(dc, ah, bC[i]); MMA16816(dc, al, bC[i]); MMA16816(dc, ah, bC[i] + 2);
        }

        if (kq) {
            float* s = redA + (((kq - 1) * 4 + cg) * 32 + lane) * 12;
            *(float4*)(s + 0) = make_float4(dz[0], dz[1], dz[2], dz[3]);
            *(float4*)(s + 4) = make_float4(dr[0], dr[1], dr[2], dr[3]);
            *(float4*)(s + 8) = make_float4(dc[0], dc[1], dc[2], dc[3]);
        }
        __syncthreads();

        float hnA[4];
        if (kq == 0) {
#pragma unroll
            for (int s3 = 0; s3 < 3; ++s3) {
                const float* s = redA + ((s3 * 4 + cg) * 32 + lane) * 12;
                const float4 vz = *(const float4*)(s + 0);
                const float4 vr = *(const float4*)(s + 4);
                const float4 vc = *(const float4*)(s + 8);
                dz[0] += vz.x; dz[1] += vz.y; dz[2] += vz.z; dz[3] += vz.w;
                dr[0] += vr.x; dr[1] += vr.y; dr[2] += vr.z; dr[3] += vr.w;
                dc[0] += vc.x; dc[1] += vc.y; dc[2] += vc.z; dc[3] += vc.w;
            }
#pragma unroll
            for (int i = 0; i < 4; ++i) {
                const int rs = i >> 1;
                const float wzv = (i & 1) ? wxv[0][rs].y : wxv[0][rs].x;
                const float wrv = (i & 1) ? wxv[1][rs].y : wxv[1][rs].x;
                const float wcv = (i & 1) ? wxv[2][rs].y : wxv[2][rs].x;
                const float z  = sigmoidf_(wzv + dz[i]);
                const float rg = sigmoidf_(wrv + dr[i]);
                const float cc = tanhf_(wcv + rg * dc[i]);
                hnA[i] = z * hpA[i] + (1.f - z) * cc;
                hpA[i] = hnA[i];
            }
            char* ex = (char*)hx + (size_t)(nb * 16 + gA) * A_BYTES;
            uint32_t hw[2], lw[2];
            hw[0] = pack_hi2(hnA[0], hnA[1], lw[0]);
            hw[1] = pack_hi2(hnA[2], hnA[3], lw[1]);
            *(uint32_t*)(ex + po1)         = hw[0];
            *(uint32_t*)(ex + po2)         = hw[1];
            *(uint32_t*)(ex + 12288 + po1) = lw[0];
            *(uint32_t*)(ex + 12288 + po2) = lw[1];
        }

        asm volatile("barrier.cluster.arrive.aligned;" ::: "memory");   // alpha

        if (kq == 0) {
            float* o1 = out_x + (browA1 * SEQ + t) * HID + hidg;
            float* o2 = out_x + (browA2 * SEQ + t) * HID + hidg;
            *(float2*)o1 = make_float2(hnA[0], hnA[1]);
            *(float2*)o2 = make_float2(hnA[2], hnA[3]);
            if (t == SEQ - 1) {
                *(float2*)(hT_out + browA1 * 512 + hidg) = make_float2(hnA[0], hnA[1]);
                *(float2*)(hT_out + browA2 * 512 + hidg) = make_float2(hnA[2], hnA[3]);
            }
        }

        // =================== B half (hides alpha flight/skew) ===================
        if (kq == 0) {
            const float* p1 = wx + (browB1 * SEQ + t) * G3 + hidg;
            const float* p2 = wx + (browB2 * SEQ + t) * G3 + hidg;
            wxv[0][0] = *(const float2*)(p1);       wxv[0][1] = *(const float2*)(p2);
            wxv[1][0] = *(const float2*)(p1 + 256); wxv[1][1] = *(const float2*)(p2 + 256);
            wxv[2][0] = *(const float2*)(p1 + 512); wxv[2][1] = *(const float2*)(p2 + 512);
        }

#pragma unroll
        for (int i = 0; i < 4; ++i) { dz[i] = 0.f; dr[i] = 0.f; dc[i] = 0.f; }
#pragma unroll
        for (int i = 0; i < 4; ++i) {
            const int ktl = (kq << 2) + i;
            uint32_t ah[4], al[4];
            const uint32_t ab = sA1u + (uint32_t)(ktl * 768) + aoff;
            LDSM4(ah, ab);
            LDSM4(al, ab + 12288);
            MMA16816(dz, ah, bZ[i]); MMA16816(dz, al, bZ[i]); MMA16816(dz, ah, bZ[i] + 2);
            MMA16816(dr, ah, bR[i]); MMA16816(dr, al, bR[i]); MMA16816(dr, ah, bR[i] + 2);
            MMA16816(dc, ah, bC[i]); MMA16816(dc, al, bC[i]); MMA16816(dc, ah, bC[i] + 2);
        }

        if (kq) {
            float* s = redB + (((kq - 1) * 4 + cg) * 32 + lane) * 12;
            *(float4*)(s + 0) = make_float4(dz[0], dz[1], dz[2], dz[3]);
            *(float4*)(s + 4) = make_float4(dr[0], dr[1], dr[2], dr[3]);
            *(float4*)(s + 8) = make_float4(dc[0], dc[1], dc[2], dc[3]);
        }
        __syncthreads();

        float hnB[4];
        if (kq == 0) {
#pragma unroll
            for (int s3 = 0; s3 < 3; ++s3) {
                const float* s = redB + ((s3 * 4 + cg) * 32 + lane) * 12;
                const float4 vz = *(const float4*)(s + 0);
                const float4 vr = *(const float4*)(s + 4);
                const float4 vc = *(const float4*)(s + 8);
                dz[0] += vz.x; dz[1] += vz.y; dz[2] += vz.z; dz[3] += vz.w;
                dr[0] += vr.x; dr[1] += vr.y; dr[2] += vr.z; dr[3] += vr.w;
                dc[0] += vc.x; dc[1] += vc.y; dc[2] += vc.z; dc[3] += vc.w;
            }
#pragma unroll
            for (int i = 0; i < 4; ++i) {
                const int rs = i >> 1;
                const float wzv = (i & 1) ? wxv[0][rs].y : wxv[0][rs].x;
                const float wrv = (i & 1) ? wxv[1][rs].y : wxv[1][rs].x;
                const float wcv = (i & 1) ? wxv[2][rs].y : wxv[2][rs].x;
                const float z  = sigmoidf_(wzv + dz[i]);
                const float rg = sigmoidf_(wrv + dr[i]);
                const float cc = tanhf_(wcv + rg * dc[i]);
                hnB[i] = z * hpB[i] + (1.f - z) * cc;
                hpB[i] = hnB[i];
            }
            char* ex = (char*)hx + (size_t)(nb * 16 + gB) * A_BYTES;
            uint32_t hw[2], lw[2];
            hw[0] = pack_hi2(hnB[0], hnB[1], lw[0]);
            hw[1] = pack_hi2(hnB[2], hnB[3], lw[1]);
            *(uint32_t*)(ex + po1)         = hw[0];
            *(uint32_t*)(ex + po2)         = hw[1];
            *(uint32_t*)(ex + 12288 + po1) = lw[0];
            *(uint32_t*)(ex + 12288 + po2) = lw[1];
        }

        asm volatile("barrier.cluster.wait.aligned;" ::: "memory");     // alpha done
        asm volatile("barrier.cluster.arrive.aligned;" ::: "memory");   // beta

        if (kq == 0) {
            float* o1 = out_x + (browB1 * SEQ + t) * HID + hidg;
            float* o2 = out_x + (browB2 * SEQ + t) * HID + hidg;
            *(float2*)o1 = make_float2(hnB[0], hnB[1]);
            *(float2*)o2 = make_float2(hnB[2], hnB[3]);
            if (t == SEQ - 1) {
                *(float2*)(hT_out + browB1 * 512 + hidg) = make_float2(hnB[0], hnB[1]);
                *(float2*)(hT_out + browB2 * 512 + hidg) = make_float2(hnB[2], hnB[3]);
            }
        }

        // reload group A image (A(t+1) visible after alpha) — hides beta flight
        {
            const uint4* src = (const uint4*)((const char*)hx +
                                              (size_t)(nb * 16 + gA) * A_BYTES);
            uint4* dst = (uint4*)sA0;
#pragma unroll
            for (int i = 0; i < 3; ++i)
                dst[tid + 512 * i] = src[tid + 512 * i];
        }

        asm volatile("barrier.cluster.wait.aligned;" ::: "memory");     // beta done

        // reload group B image (B(t+1) now visible)
        {
            const uint4* src = (const uint4*)((const char*)hx +
                                              (size_t)(nb * 16 + gB) * A_BYTES);
            uint4* dst = (uint4*)sA1;
#pragma unroll
            for (int i = 0; i < 3; ++i)
                dst[tid + 512 * i] = src[tid + 512 * i];
        }
        __syncthreads();   // both reloads visible CTA-wide before next iteration
    }
}

// ---------------------------------------------------------------------------
// Launch  (pack, ueff, s1wx, rnn, s1wx, rnn — rnn profiled @#4)
// ---------------------------------------------------------------------------
extern "C" void kernel_launch(void* const* d_in, const int* in_sizes, int n_in,
                              void* d_out, int out_size)
{
    const float* x   = (const float*)d_in[0];
    const float* Wd  = (const float*)d_in[1];
    const float* Wdg = (const float*)d_in[2];
    const float* Wo  = (const float*)d_in[3];
    const float* Wog = (const float*)d_in[4];
    const float* Ud  = (const float*)d_in[5];
    const float* Udg = (const float*)d_in[6];
    const float* Uo  = (const float*)d_in[7];
    const float* Uog = (const float*)d_in[8];
    const float* bb  = (const float*)d_in[9];
    float* out = (float*)d_out;

    float *pWX, *pX1, *pPu, *pQu;
    __nv_bfloat16 *pUhi, *pUlo, *pHX, *pQ16, *pP16;
    cudaGetSymbolAddress((void**)&pWX,   g_wx_buf);
    cudaGetSymbolAddress((void**)&pX1,   g_x1);
    cudaGetSymbolAddress((void**)&pPu,   g_Pu);
    cudaGetSymbolAddress((void**)&pQu,   g_Qu);
    cudaGetSymbolAddress((void**)&pUhi,  g_Uhi);
    cudaGetSymbolAddress((void**)&pUlo,  g_Ulo);
    cudaGetSymbolAddress((void**)&pHX,   g_hx);
    cudaGetSymbolAddress((void**)&pQ16,  g_q16);
    cudaGetSymbolAddress((void**)&pP16,  g_p16);

    cudaFuncSetAttribute(rnn_hmma, cudaFuncAttributeMaxDynamicSharedMemorySize,
                         RNN_SMEM);
    cudaFuncSetAttribute(s1wx_hmma, cudaFuncAttributeMaxDynamicSharedMemorySize,
                         FX_SMEM);

    pack_kernel<<<(LAYERS * RANKSUM * G3 + 255) / 256, 256>>>(Wd, Wdg, Wo, Wog,
                                                              Ud, Udg, Uo, Uog);
    gemm_ueff<<<dim3(HID / 64, G3 / 64, LAYERS), 256>>>(pPu, pQu);

    const size_t OUT0 = (size_t)ROWS * HID;

    for (int l = 0; l < LAYERS; ++l) {
        const float* xin = (l == 0) ? x : pX1;
        s1wx_hmma<<<ROWS / 128, 256, FX_SMEM>>>(
            xin, pP16 + (size_t)l * 96 * 512, pQ16 + (size_t)l * G3 * 192,
            bb + l * G3, pWX);
        float* ox = (l == LAYERS - 1) ? out : pX1;
        rnn_hmma<<<64, 512, RNN_SMEM>>>(
            pUhi + (size_t)l * 8 * BTILE, pUlo + (size_t)l * 8 * BTILE,
            pWX, ox, out + OUT0 + l * HID, pHX);
    }
}

// round 17
// speedup vs baseline: 1.1074x; 1.1074x over previous
#include <cuda_runtime.h>
#include <cuda_bf16.h>
#include <cstdint>
#include <cstddef>

// ---------------------------------------------------------------------------
// Problem constants
// ---------------------------------------------------------------------------
#define BATCH   256
#define SEQ     512
#define NIN     256
#define HID     256
#define G3      768
#define LAYERS  2
#define ROWS    (BATCH*SEQ)
#define RANKSUM 96

// ---------------------------------------------------------------------------
// Static device scratch (no cudaMalloc allowed)
// ---------------------------------------------------------------------------
__device__ float g_wx_buf[(size_t)ROWS * G3];
__device__ float g_x1[(size_t)ROWS * HID];
__device__ float g_Pu[LAYERS * HID * RANKSUM];
__device__ float g_Qu[LAYERS * RANKSUM * G3];

// Q as bf16 hi/lo: [layer][n 768][hi 96 | lo 96]
__device__ __nv_bfloat16 g_q16[(size_t)LAYERS * G3 * 192];
// P^T as bf16 hi/lo: [layer][n 96][hi 256 | lo 256]
__device__ __nv_bfloat16 g_p16[(size_t)LAYERS * 96 * 512];

// U as bf16 hi/lo in B-operand layout: per (layer, cta): [96 n][264 k-padded]
#define BPAD  264                         // 528 bytes per row (bank step 4)
#define BTILE (96 * BPAD)                 // elems per (l, c) per precision
__device__ __nv_bfloat16 g_Uhi[(size_t)LAYERS * 8 * BTILE];
__device__ __nv_bfloat16 g_Ulo[(size_t)LAYERS * 8 * BTILE];

// h exchange (L2), MMA A-FRAGMENT layout:
// [buf 2][group 16][ktl 16][prec 2][lane 32][4 x u32]  = 16KB per group
#define AF_BYTES 16384
__device__ __nv_bfloat16 g_hx[2 * 16 * (AF_BYTES / 2)];

// ---------------------------------------------------------------------------
// PTX helpers (baseline-target-safe: ldmatrix + mma.sync only)
// ---------------------------------------------------------------------------
__device__ __forceinline__ uint32_t smem_u32(const void* p)
{
    uint32_t a;
    asm("{ .reg .u64 t; cvta.to.shared.u64 t, %1; cvt.u32.u64 %0, t; }"
        : "=r"(a) : "l"(p));
    return a;
}

#define LDSM4(R, addr) \
    asm volatile("ldmatrix.sync.aligned.m8n8.x4.shared.b16 {%0,%1,%2,%3}, [%4];" \
        : "=r"((R)[0]), "=r"((R)[1]), "=r"((R)[2]), "=r"((R)[3]) : "r"(addr))
#define MMA16816(D, A, B) \
    asm volatile("mma.sync.aligned.m16n8k16.row.col.f32.bf16.bf16.f32 " \
        "{%0,%1,%2,%3}, {%4,%5,%6,%7}, {%8,%9}, {%0,%1,%2,%3};" \
        : "+f"((D)[0]), "+f"((D)[1]), "+f"((D)[2]), "+f"((D)[3]) \
        : "r"((A)[0]), "r"((A)[1]), "r"((A)[2]), "r"((A)[3]), \
          "r"((B)[0]), "r"((B)[1]))

__device__ __forceinline__ uint32_t pack_hi2(float a, float b, uint32_t& lo)
{
    __nv_bfloat16 h0 = __float2bfloat16(a);
    __nv_bfloat16 h1 = __float2bfloat16(b);
    __nv_bfloat16 l0 = __float2bfloat16(a - __bfloat162float(h0));
    __nv_bfloat16 l1 = __float2bfloat16(b - __bfloat162float(h1));
    lo = (uint32_t)__bfloat16_as_ushort(l0) |
         ((uint32_t)__bfloat16_as_ushort(l1) << 16);
    return (uint32_t)__bfloat16_as_ushort(h0) |
           ((uint32_t)__bfloat16_as_ushort(h1) << 16);
}

// ---------------------------------------------------------------------------
// Pack kernel: Pu/Qu (fp32, for ueff) + q16/p16 hi/lo (direct from inputs)
// ---------------------------------------------------------------------------
__global__ void pack_kernel(const float* __restrict__ Wd, const float* __restrict__ Wdg,
                            const float* __restrict__ Wo, const float* __restrict__ Wog,
                            const float* __restrict__ Ud, const float* __restrict__ Udg,
                            const float* __restrict__ Uo, const float* __restrict__ Uog)
{
    int idx = blockIdx.x * 256 + threadIdx.x;
    const int QN = LAYERS * RANKSUM * G3;
    const int PN = LAYERS * NIN * RANKSUM;
    const int P16N = LAYERS * 96 * 256;
    if (idx < QN) {
        int l = idx / (RANKSUM * G3);
        int rem = idx - l * (RANKSUM * G3);
        int r = rem / G3, n = rem - r * G3;
        g_Qu[idx] = (r < 64) ? Udg[(l*64 + r) * G3 + n] : Uog[(l*32 + (r-64)) * G3 + n];
        int k = idx % 96;
        int n2 = (idx / 96) % G3;
        int l2 = idx / (96 * G3);
        float v = (k < 64) ? Wdg[(l2*64 + k) * G3 + n2]
                           : Wog[(l2*32 + (k-64)) * G3 + n2];
        __nv_bfloat16 hi = __float2bfloat16(v);
        __nv_bfloat16 lo = __float2bfloat16(v - __bfloat162float(hi));
        size_t o = ((size_t)l2 * G3 + n2) * 192 + k;
        g_q16[o]      = hi;
        g_q16[o + 96] = lo;
    }
    if (idx < PN) {
        int l = idx / (NIN * RANKSUM);
        int rem = idx - l * (NIN * RANKSUM);
        int k = rem / RANKSUM, j = rem - k * RANKSUM;
        g_Pu[idx] = (j < 64) ? Ud[(l*NIN + k) * 64 + j] : Uo[(l*NIN + k) * 32 + (j-64)];
    }
    if (idx < P16N) {
        int k = idx & 255;
        int n = (idx >> 8) % 96;
        int l = idx / (96 * 256);
        float v = (n < 64) ? Wd[(l*NIN + k) * 64 + n]
                           : Wo[(l*NIN + k) * 32 + (n-64)];
        __nv_bfloat16 hi = __float2bfloat16(v);
        __nv_bfloat16 lo = __float2bfloat16(v - __bfloat162float(hi));
        size_t o = ((size_t)l * 96 + n) * 512 + k;
        g_p16[o]       = hi;
        g_p16[o + 256] = lo;
    }
}

// ---------------------------------------------------------------------------
// Ueff GEMM with fused hi/lo B-layout split epilogue.
// ---------------------------------------------------------------------------
__global__ void __launch_bounds__(256)
gemm_ueff(const float* __restrict__ Pu, const float* __restrict__ Qu)
{
    __shared__ float As[16][64];
    __shared__ float Bs[16][68];

    const int l = blockIdx.z;
    const float* A = Pu + (size_t)l * HID * RANKSUM;
    const float* B = Qu + (size_t)l * RANKSUM * G3;

    const int tid = threadIdx.x;
    const int tm = tid >> 4, tn = tid & 15;
    const int bm = blockIdx.x * 64;
    const int bn = blockIdx.y * 64;

    const int ar = tid >> 2, ak = (tid & 3) << 2;
    const int brow = tid >> 4, bcol = (tid & 15) << 2;

    float acc[4][4];
#pragma unroll
    for (int i = 0; i < 4; ++i)
#pragma unroll
        for (int j = 0; j < 4; ++j) acc[i][j] = 0.f;

    for (int k0 = 0; k0 < RANKSUM; k0 += 16) {
        float4 av = *(const float4*)(A + (bm + ar) * RANKSUM + k0 + ak);
        As[ak + 0][ar] = av.x; As[ak + 1][ar] = av.y;
        As[ak + 2][ar] = av.z; As[ak + 3][ar] = av.w;

        float4 bv = *(const float4*)(B + (size_t)(k0 + brow) * G3 + bn + bcol);
        *(float4*)&Bs[brow][bcol] = bv;
        __syncthreads();

#pragma unroll
        for (int k = 0; k < 16; ++k) {
            float4 a = *(const float4*)&As[k][tm << 2];
            float4 b = *(const float4*)&Bs[k][tn << 2];
            acc[0][0] = fmaf(a.x, b.x, acc[0][0]); acc[0][1] = fmaf(a.x, b.y, acc[0][1]);
            acc[0][2] = fmaf(a.x, b.z, acc[0][2]); acc[0][3] = fmaf(a.x, b.w, acc[0][3]);
            acc[1][0] = fmaf(a.y, b.x, acc[1][0]); acc[1][1] = fmaf(a.y, b.y, acc[1][1]);
            acc[1][2] = fmaf(a.y, b.z, acc[1][2]); acc[1][3] = fmaf(a.y, b.w, acc[1][3]);
            acc[2][0] = fmaf(a.z, b.x, acc[2][0]); acc[2][1] = fmaf(a.z, b.y, acc[2][1]);
            acc[2][2] = fmaf(a.z, b.z, acc[2][2]); acc[2][3] = fmaf(a.z, b.w, acc[2][3]);
            acc[3][0] = fmaf(a.w, b.x, acc[3][0]); acc[3][1] = fmaf(a.w, b.y, acc[3][1]);
            acc[3][2] = fmaf(a.w, b.z, acc[3][2]); acc[3][3] = fmaf(a.w, b.w, acc[3][3]);
        }
        __syncthreads();
    }

#pragma unroll
    for (int i = 0; i < 4; ++i) {
        int k = bm + (tm << 2) + i;
#pragma unroll
        for (int j = 0; j < 4; ++j) {
            int col = bn + (tn << 2) + j;
            int c = (col >> 5) & 7;
            int n = ((col >> 8) << 5) + (col & 31);
            float v = acc[i][j];
            __nv_bfloat16 hi = __float2bfloat16(v);
            __nv_bfloat16 lo = __float2bfloat16(v - __bfloat162float(hi));
            size_t o = ((size_t)l * 8 + c) * BTILE + n * BPAD + k;
            g_Uhi[o] = hi;
            g_Ulo[o] = lo;
        }
    }
}

// ---------------------------------------------------------------------------
// Fused stage-1 + stage-2 GEMM (unchanged R15 winner)
// ---------------------------------------------------------------------------
#define FX_T_BYTES (128 * 416)
#define FX_B_BYTES (64 * 416)
#define FX_SMEM    (FX_T_BYTES + FX_B_BYTES)

__global__ void __launch_bounds__(256)
s1wx_hmma(const float* __restrict__ x,
          const __nv_bfloat16* __restrict__ P16,
          const __nv_bfloat16* __restrict__ Q16,
          const float* __restrict__ bias,
          float* __restrict__ C)
{
    extern __shared__ char sm[];
    char* sT = sm;
    char* sB = sm + FX_T_BYTES;

    const int tid = threadIdx.x;
    const int w = tid >> 5, lane = tid & 31;
    const int wm = w >> 1, wn = w & 1;
    const size_t bm = (size_t)blockIdx.x * 128;

    const uint32_t sTu = smem_u32(sT);
    const uint32_t sBu = smem_u32(sB);

    const int rr = lane & 7;
    const int q = lane >> 3;
    const int er = lane >> 2;
    const int ec = (lane & 3) << 1;

    // ================= phase 1: T = x @ P16^T =================
    {
        const uint32_t a1off = (uint32_t)((wm * 32 + ((lane >> 3) & 1) * 8 + rr) * 272
                                          + (lane >> 4) * 16);
        const uint32_t b1off = (uint32_t)(rr * 272 + ((q >> 1) * 128) + (q & 1) * 16);

        float acc1[2][6][4];
#pragma unroll
        for (int mt = 0; mt < 2; ++mt)
#pragma unroll
            for (int nt = 0; nt < 6; ++nt)
#pragma unroll
                for (int i = 0; i < 4; ++i) acc1[mt][nt][i] = 0.f;

        const int crow = tid >> 1, chalf = tid & 1;

        for (int kc = 0; kc < 4; ++kc) {
            {
                const float4* src = (const float4*)(x + (bm + crow) * NIN
                                                    + kc * 64 + chalf * 32);
                char* dst = sT + crow * 272 + chalf * 64;
#pragma unroll
                for (int i = 0; i < 8; ++i) {
                    float4 v = src[i];
                    uint32_t lw0, lw1;
                    uint32_t hw0 = pack_hi2(v.x, v.y, lw0);
                    uint32_t hw1 = pack_hi2(v.z, v.w, lw1);
                    *(uint32_t*)(dst + i * 8)           = hw0;
                    *(uint32_t*)(dst + i * 8 + 4)       = hw1;
                    *(uint32_t*)(dst + 128 + i * 8)     = lw0;
                    *(uint32_t*)(dst + 128 + i * 8 + 4) = lw1;
                }
            }
            {
#pragma unroll
                for (int it = 0; it < 6; ++it) {
                    int u = tid + 256 * it;
                    int n = u >> 4;
                    int part = (u >> 3) & 1;
                    int i = u & 7;
                    const uint4* src = (const uint4*)(P16 + (size_t)n * 512
                                                      + part * 256 + kc * 64) + i;
                    *(uint4*)(sB + n * 272 + part * 128 + i * 16) = *src;
                }
            }
            __syncthreads();

#pragma unroll
            for (int kt = 0; kt < 4; ++kt) {
                uint32_t ahi[2][4], alo[2][4];
#pragma unroll
                for (int mt = 0; mt < 2; ++mt) {
                    const uint32_t ab = sTu + a1off
                                      + (uint32_t)(mt * 16 * 272 + kt * 32);
                    LDSM4(ahi[mt], ab);
                    LDSM4(alo[mt], ab + 128);
                }
#pragma unroll
                for (int nt = 0; nt < 6; ++nt) {
                    uint32_t bf[4];
                    LDSM4(bf, sBu + b1off
                              + (uint32_t)((wn * 48 + nt * 8) * 272 + kt * 32));
#pragma unroll
                    for (int mt = 0; mt < 2; ++mt) {
                        MMA16816(acc1[mt][nt], ahi[mt], bf);
                        MMA16816(acc1[mt][nt], alo[mt], bf);
                        MMA16816(acc1[mt][nt], ahi[mt], bf + 2);
                    }
                }
            }
            __syncthreads();
        }

#pragma unroll
        for (int nt = 0; nt < 6; ++nt) {
            const int col = wn * 48 + nt * 8 + ec;
#pragma unroll
            for (int mt = 0; mt < 2; ++mt) {
#pragma unroll
                for (int rh = 0; rh < 2; ++rh) {
                    const int rowl = wm * 32 + mt * 16 + er + rh * 8;
                    uint32_t lw;
                    uint32_t hw = pack_hi2(acc1[mt][nt][rh * 2],
                                           acc1[mt][nt][rh * 2 + 1], lw);
                    *(uint32_t*)(sT + rowl * 416 + col * 2)       = hw;
                    *(uint32_t*)(sT + rowl * 416 + 208 + col * 2) = lw;
                }
            }
        }
        __syncthreads();
    }

    // ================= phase 2: wx = T @ Q16^T + bias =================
    {
        const uint32_t a2off = (uint32_t)((wm * 32 + ((lane >> 3) & 1) * 8 + rr) * 416
                                          + (lane >> 4) * 16);
        const uint32_t b2off = (uint32_t)((wn * 32 + rr) * 416 + (q & 1) * 16
                                          + (q >> 1) * 208);

        for (int bnc = 0; bnc < 12; ++bnc) {
            {
                const uint4* srcB = (const uint4*)Q16 + (size_t)(bnc * 64) * 24;
#pragma unroll
                for (int i = 0; i < 6; ++i) {
                    int u = tid + 256 * i;
                    int row = u / 24, ir = u - row * 24;
                    uint32_t off = (uint32_t)(row * 416 + ir * 16
                                              + ((ir >= 12) ? 16 : 0));
                    *(uint4*)(sB + off) = srcB[u];
                }
            }
            __syncthreads();

            float acc2[2][4][4];
#pragma unroll
            for (int mt = 0; mt < 2; ++mt)
#pragma unroll
                for (int nt = 0; nt < 4; ++nt)
#pragma unroll
                    for (int i = 0; i < 4; ++i) acc2[mt][nt][i] = 0.f;

#pragma unroll
            for (int kt = 0; kt < 6; ++kt) {
                uint32_t ahi[2][4], alo[2][4];
#pragma unroll
                for (int mt = 0; mt < 2; ++mt) {
                    const uint32_t ab = sTu + a2off
                                      + (uint32_t)(mt * 16 * 416 + kt * 32);
                    LDSM4(ahi[mt], ab);
                    LDSM4(alo[mt], ab + 208);
                }
#pragma unroll
                for (int nt = 0; nt < 4; ++nt) {
                    uint32_t bf[4];
                    LDSM4(bf, sBu + b2off + (uint32_t)(nt * 8 * 416 + kt * 32));
#pragma unroll
                    for (int mt = 0; mt < 2; ++mt) {
                        MMA16816(acc2[mt][nt], ahi[mt], bf);
                        MMA16816(acc2[mt][nt], alo[mt], bf);
                        MMA16816(acc2[mt][nt], ahi[mt], bf + 2);
                    }
                }
            }

#pragma unroll
            for (int nt = 0; nt < 4; ++nt) {
                const int col = bnc * 64 + wn * 32 + nt * 8 + ec;
                const float b0 = bias[col], b1 = bias[col + 1];
#pragma unroll
                for (int mt = 0; mt < 2; ++mt) {
                    const size_t r0 = bm + wm * 32 + mt * 16 + er;
                    *(float2*)(C + r0 * G3 + col) =
                        make_float2(acc2[mt][nt][0] + b0, acc2[mt][nt][1] + b1);
                    *(float2*)(C + (r0 + 8) * G3 + col) =
                        make_float2(acc2[mt][nt][2] + b0, acc2[mt][nt][3] + b1);
                }
            }
            __syncthreads();
        }
    }
}

__device__ __forceinline__ float sigmoidf_(float x)
{
    return __fdividef(1.f, 1.f + __expf(-x));
}
__device__ __forceinline__ float tanhf_(float x)
{
    return __fdividef(2.f, 1.f + __expf(-2.f * x)) - 1.f;
}

// ---------------------------------------------------------------------------
// HMMA recurrent kernel v8: R15 structure, exchange in MMA A-FRAGMENT layout.
// Exchange record: [ktl 16][prec 2][lane 32][a0 a1 a2 a3] (16KB/group).
// Publisher thread's 4 h values == consumer regs {a0,a1} or {a2,a3} of
// consumer thread lane_c == lane -> publish = 2 x STG.64.
// In-loop A access = 1 LDS.128 per (ktl, prec), no ldmatrix, no swizzle.
// Reload = 2 LDG.128 + 2 STS.128 per thread (16KB, was 24KB).
// ---------------------------------------------------------------------------
#define B_BYTES  (BTILE * 2)
#define RED_BYTES (3 * 4 * 32 * 12 * 4)
#define RNN_SMEM (AF_BYTES + 2 * B_BYTES + RED_BYTES)   // 16384+101376+18432

__global__ void __cluster_dims__(8, 1, 1) __launch_bounds__(512, 1)
rnn_hmma(const __nv_bfloat16* __restrict__ Uhi8,
         const __nv_bfloat16* __restrict__ Ulo8,
         const float* __restrict__ wx,
         float* __restrict__ out_x,
         float* __restrict__ hT_out,
         __nv_bfloat16* __restrict__ hx)
{
    extern __shared__ char sm[];
    char* sA  = sm;                       // fragment image, 16KB
    char* sBh = sm + AF_BYTES;
    char* sBl = sBh + B_BYTES;
    float* red = (float*)(sBl + B_BYTES);

    const int c  = blockIdx.x & 7;
    const int g  = blockIdx.x >> 3;
    const int tid = threadIdx.x;
    const int w = tid >> 5, lane = tid & 31;
    const int kq = w >> 2;
    const int cg = w & 3;

    {
        const uint4* s0 = (const uint4*)(Uhi8 + (size_t)c * BTILE);
        const uint4* s1 = (const uint4*)(Ulo8 + (size_t)c * BTILE);
        uint4* d0 = (uint4*)sBh;
        uint4* d1 = (uint4*)sBl;
        for (int i = tid; i < B_BYTES / 16; i += 512) { d0[i] = s0[i]; d1[i] = s1[i]; }
        uint4 z4 = make_uint4(0u, 0u, 0u, 0u);
        uint4* a4 = (uint4*)sA;
        for (int i = tid; i < AF_BYTES / 16; i += 512) a4[i] = z4;
    }
    __syncthreads();

    const uint32_t sBhu = smem_u32(sBh);
    const uint32_t sBlu = smem_u32(sBl);
    const int q = lane >> 3, rr = lane & 7;
    const uint32_t bbase = ((q < 2) ? sBhu : sBlu)
                         + (uint32_t)(rr * 528 + (q & 1) * 16)
                         + (uint32_t)((cg << 3) * 528);
    const uint32_t bz = 0, br = 32 * 528, bc = 64 * 528;

    // hoist B fragments (time-invariant) into registers
    uint32_t bZ[4][4], bR[4][4], bC[4][4];
#pragma unroll
    for (int i = 0; i < 4; ++i) {
        const uint32_t ko = bbase + (uint32_t)(((kq << 2) + i) * 32);
        LDSM4(bZ[i], ko + bz);
        LDSM4(bR[i], ko + br);
        LDSM4(bC[i], ko + bc);
    }

    const int r1 = lane >> 2;
    const int coll = (cg << 3) + ((lane & 3) << 1);
    const int hidg = (c << 5) + coll;
    const size_t brow1 = (size_t)(g * 16 + r1);
    const size_t brow2 = brow1 + 8;

    // publish offsets into the fragment-layout exchange image
    const int ktl_c = (c << 1) + (cg >> 1);
    const uint32_t fo_hi = (uint32_t)((((ktl_c << 1) + 0) * 32 + lane) * 16
                                      + ((cg & 1) << 3));
    const uint32_t fo_lo = fo_hi + 512;

    float hp[4] = {0.f, 0.f, 0.f, 0.f};

    float2 wxv[3][2];
    if (kq == 0) {
        const float* p1 = wx + (brow1 * SEQ) * G3 + hidg;
        const float* p2 = wx + (brow2 * SEQ) * G3 + hidg;
        wxv[0][0] = *(const float2*)(p1);       wxv[0][1] = *(const float2*)(p2);
        wxv[1][0] = *(const float2*)(p1 + 256); wxv[1][1] = *(const float2*)(p2 + 256);
        wxv[2][0] = *(const float2*)(p1 + 512); wxv[2][1] = *(const float2*)(p2 + 512);
    }

    for (int t = 0; t < SEQ; ++t) {
        float2 wxn[3][2];
        if (kq == 0) {
            const int tn = (t + 1 < SEQ) ? t + 1 : t;
            const float* p1 = wx + (brow1 * SEQ + tn) * G3 + hidg;
            const float* p2 = wx + (brow2 * SEQ + tn) * G3 + hidg;
            wxn[0][0] = *(const float2*)(p1);       wxn[0][1] = *(const float2*)(p2);
            wxn[1][0] = *(const float2*)(p1 + 256); wxn[1][1] = *(const float2*)(p2 + 256);
            wxn[2][0] = *(const float2*)(p1 + 512); wxn[2][1] = *(const float2*)(p2 + 512);
        }

        float dz[4] = {0.f, 0.f, 0.f, 0.f};
        float dr[4] = {0.f, 0.f, 0.f, 0.f};
        float dc[4] = {0.f, 0.f, 0.f, 0.f};
#pragma unroll
        for (int i = 0; i < 4; ++i) {
            const int ktl = (kq << 2) + i;
            uint32_t ah[4], al[4];
            // fragment records: contiguous 16B per (ktl, prec, lane)
            *(uint4*)ah = *(const uint4*)(sA + (((ktl << 1) + 0) * 32 + lane) * 16);
            *(uint4*)al = *(const uint4*)(sA + (((ktl << 1) + 1) * 32 + lane) * 16);

            MMA16816(dz, ah, bZ[i]);
            MMA16816(dz, al, bZ[i]);
            MMA16816(dz, ah, bZ[i] + 2);

            MMA16816(dr, ah, bR[i]);
            MMA16816(dr, al, bR[i]);
            MMA16816(dr, ah, bR[i] + 2);

            MMA16816(dc, ah, bC[i]);
            MMA16816(dc, al, bC[i]);
            MMA16816(dc, ah, bC[i] + 2);
        }

        if (kq) {
            float* s = red + (((kq - 1) * 4 + cg) * 32 + lane) * 12;
            *(float4*)(s + 0) = make_float4(dz[0], dz[1], dz[2], dz[3]);
            *(float4*)(s + 4) = make_float4(dr[0], dr[1], dr[2], dr[3]);
            *(float4*)(s + 8) = make_float4(dc[0], dc[1], dc[2], dc[3]);
        }
        __syncthreads();

        float hn[4];
        if (kq == 0) {
#pragma unroll
            for (int s3 = 0; s3 < 3; ++s3) {
                const float* s = red + ((s3 * 4 + cg) * 32 + lane) * 12;
                const float4 vz = *(const float4*)(s + 0);
                const float4 vr = *(const float4*)(s + 4);
                const float4 vc = *(const float4*)(s + 8);
                dz[0] += vz.x; dz[1] += vz.y; dz[2] += vz.z; dz[3] += vz.w;
                dr[0] += vr.x; dr[1] += vr.y; dr[2] += vr.z; dr[3] += vr.w;
                dc[0] += vc.x; dc[1] += vc.y; dc[2] += vc.z; dc[3] += vc.w;
            }

#pragma unroll
            for (int i = 0; i < 4; ++i) {
                const int rs = i >> 1;
                const float wzv = (i & 1) ? wxv[0][rs].y : wxv[0][rs].x;
                const float wrv = (i & 1) ? wxv[1][rs].y : wxv[1][rs].x;
                const float wcv = (i & 1) ? wxv[2][rs].y : wxv[2][rs].x;
                const float z  = sigmoidf_(wzv + dz[i]);
                const float rg = sigmoidf_(wrv + dr[i]);
                const float cc = tanhf_(wcv + rg * dc[i]);
                hn[i] = z * hp[i] + (1.f - z) * cc;
                hp[i] = hn[i];
            }

            // publish directly in fragment layout:
            //   reg pair (row r1, row r1+8) for k-pair (coll, coll+1)
            const int nb = (t + 1) & 1;
            char* ex = (char*)hx + (size_t)(nb * 16 + g) * AF_BYTES;
            uint32_t lw0, lw1;
            uint32_t hw0 = pack_hi2(hn[0], hn[1], lw0);   // row r1
            uint32_t hw1 = pack_hi2(hn[2], hn[3], lw1);   // row r1+8
            *(uint2*)(ex + fo_hi) = make_uint2(hw0, hw1);
            *(uint2*)(ex + fo_lo) = make_uint2(lw0, lw1);
        }

        asm volatile("barrier.cluster.arrive.aligned;" ::: "memory");

        if (kq == 0) {
            float* o1 = out_x + (brow1 * SEQ + t) * HID + hidg;
            float* o2 = out_x + (brow2 * SEQ + t) * HID + hidg;
            *(float2*)o1 = make_float2(hn[0], hn[1]);
            *(float2*)o2 = make_float2(hn[2], hn[3]);
            if (t == SEQ - 1) {
                *(float2*)(hT_out + brow1 * 512 + hidg) = make_float2(hn[0], hn[1]);
                *(float2*)(hT_out + brow2 * 512 + hidg) = make_float2(hn[2], hn[3]);
            }
#pragma unroll
            for (int a3 = 0; a3 < 3; ++a3) {
                wxv[a3][0] = wxn[a3][0];
                wxv[a3][1] = wxn[a3][1];
            }
        }

        asm volatile("barrier.cluster.wait.aligned;" ::: "memory");

        // reload fragment image (16KB, 2 LDG.128 + 2 STS.128 per thread)
        {
            const int nb = (t + 1) & 1;
            const uint4* src = (const uint4*)((const char*)hx +
                                              (size_t)(nb * 16 + g) * AF_BYTES);
            uint4* dst = (uint4*)sA;
            dst[tid]       = src[tid];
            dst[tid + 512] = src[tid + 512];
        }
        __syncthreads();
    }
}

// ---------------------------------------------------------------------------
// Launch  (pack, ueff, s1wx, rnn, s1wx, rnn — rnn profiled @#4)
// ---------------------------------------------------------------------------
extern "C" void kernel_launch(void* const* d_in, const int* in_sizes, int n_in,
                              void* d_out, int out_size)
{
    const float* x   = (const float*)d_in[0];
    const float* Wd  = (const float*)d_in[1];
    const float* Wdg = (const float*)d_in[2];
    const float* Wo  = (const float*)d_in[3];
    const float* Wog = (const float*)d_in[4];
    const float* Ud  = (const float*)d_in[5];
    const float* Udg = (const float*)d_in[6];
    const float* Uo  = (const float*)d_in[7];
    const float* Uog = (const float*)d_in[8];
    const float* bb  = (const float*)d_in[9];
    float* out = (float*)d_out;

    float *pWX, *pX1, *pPu, *pQu;
    __nv_bfloat16 *pUhi, *pUlo, *pHX, *pQ16, *pP16;
    cudaGetSymbolAddress((void**)&pWX,   g_wx_buf);
    cudaGetSymbolAddress((void**)&pX1,   g_x1);
    cudaGetSymbolAddress((void**)&pPu,   g_Pu);
    cudaGetSymbolAddress((void**)&pQu,   g_Qu);
    cudaGetSymbolAddress((void**)&pUhi,  g_Uhi);
    cudaGetSymbolAddress((void**)&pUlo,  g_Ulo);
    cudaGetSymbolAddress((void**)&pHX,   g_hx);
    cudaGetSymbolAddress((void**)&pQ16,  g_q16);
    cudaGetSymbolAddress((void**)&pP16,  g_p16);

    cudaFuncSetAttribute(rnn_hmma, cudaFuncAttributeMaxDynamicSharedMemorySize,
                         RNN_SMEM);
    cudaFuncSetAttribute(s1wx_hmma, cudaFuncAttributeMaxDynamicSharedMemorySize,
                         FX_SMEM);

    pack_kernel<<<(LAYERS * RANKSUM * G3 + 255) / 256, 256>>>(Wd, Wdg, Wo, Wog,
                                                              Ud, Udg, Uo, Uog);
    gemm_ueff<<<dim3(HID / 64, G3 / 64, LAYERS), 256>>>(pPu, pQu);

    const size_t OUT0 = (size_t)ROWS * HID;

    for (int l = 0; l < LAYERS; ++l) {
        const float* xin = (l == 0) ? x : pX1;
        s1wx_hmma<<<ROWS / 128, 256, FX_SMEM>>>(
            xin, pP16 + (size_t)l * 96 * 512, pQ16 + (size_t)l * G3 * 192,
            bb + l * G3, pWX);
        float* ox = (l == LAYERS - 1) ? out : pX1;
        rnn_hmma<<<128, 512, RNN_SMEM>>>(
            pUhi + (size_t)l * 8 * BTILE, pUlo + (size_t)l * 8 * BTILE,
            pWX, ox, out + OUT0 + l * HID, pHX);
    }
}